// round 7
// baseline (speedup 1.0000x reference)
#include <cuda_runtime.h>

// 2x FIR upsample, depthwise separable [1,3,3,1]/4 per axis (factor=2 gain).
//   out[2i]   = 0.25*x[i-1] + 0.75*x[i]
//   out[2i+1] = 0.75*x[i]   + 0.25*x[i+1]
// Input (8,128,128,128) f32 -> Output (8,128,256,256) f32.
//
// No smem: each thread owns 2 input rows (4 cols), loads its 4-row vertical
// halo straight from GMEM (overlap between warps hits in L1), blends
// vertically in registers, horizontal upsample via 2 shfls per output row.

#define H_IN 128
#define W_IN 128
#define W_OUT 256
#define RPB 16                   // input rows per block (8 warps x 2 rows)

__device__ __forceinline__ float4 blend(float wa, float4 a, float wb, float4 b) {
    return make_float4(wa*a.x + wb*b.x, wa*a.y + wb*b.y,
                       wa*a.z + wb*b.z, wa*a.w + wb*b.w);
}

// Horizontal 2x upsample: lane l holds cols 4l..4l+3; halo via shfl
// (zero at chip edges since W=128=32*4 exactly spans the warp).
__device__ __forceinline__ void hup(float4 v, int lane, float4& lo, float4& hi) {
    float left  = __shfl_up_sync(0xFFFFFFFFu, v.w, 1);
    float right = __shfl_down_sync(0xFFFFFFFFu, v.x, 1);
    if (lane == 0)  left  = 0.f;
    if (lane == 31) right = 0.f;
    lo.x = 0.25f * left + 0.75f * v.x;
    lo.y = 0.75f * v.x  + 0.25f * v.y;
    lo.z = 0.25f * v.x  + 0.75f * v.y;
    lo.w = 0.75f * v.y  + 0.25f * v.z;
    hi.x = 0.25f * v.y  + 0.75f * v.z;
    hi.y = 0.75f * v.z  + 0.25f * v.w;
    hi.z = 0.25f * v.z  + 0.75f * v.w;
    hi.w = 0.75f * v.w  + 0.25f * right;
}

__global__ __launch_bounds__(256)
void upsample2x_fir_kernel(const float* __restrict__ x, float* __restrict__ out) {
    const int warp = threadIdx.x >> 5;                       // 0..7: row-pair in block
    const int lane = threadIdx.x & 31;

    const int rb   = blockIdx.x;                             // 0..7
    const int chan = blockIdx.z * gridDim.y + blockIdx.y;    // b*C + c
    const float* xp = x   + (size_t)chan * (H_IN * W_IN);
    float*       op = out + (size_t)chan * (2 * H_IN * W_OUT);

    const int r  = rb * RPB + 2 * warp;                      // first input row of pair
    const int jc = lane * 4;                                 // col base

    // 4 halo rows: r-1, r, r+1, r+2 (zero outside image). Front-batched LDG.128.
    const float* p = xp + (size_t)r * W_IN + jc;
    float4 m0 = (r - 1 >= 0)   ? *(const float4*)(p - W_IN)     : make_float4(0,0,0,0);
    float4 m1 =                  *(const float4*)(p);
    float4 m2 =                  *(const float4*)(p + W_IN);
    float4 m3 = (r + 2 < H_IN) ? *(const float4*)(p + 2 * W_IN) : make_float4(0,0,0,0);

    // Vertical blends -> 4 output rows.
    const float4 e0 = blend(0.25f, m0, 0.75f, m1);   // out row 2r
    const float4 o0 = blend(0.75f, m1, 0.25f, m2);   // out row 2r+1
    const float4 e1 = blend(0.25f, m1, 0.75f, m2);   // out row 2r+2
    const float4 o1 = blend(0.75f, m2, 0.25f, m3);   // out row 2r+3

    float* q = op + (size_t)(2 * r) * W_OUT + 2 * jc;

    float4 lo, hi;
    hup(e0, lane, lo, hi);
    *(float4*)(q)                 = lo;  *(float4*)(q + 4)             = hi;
    hup(o0, lane, lo, hi);
    *(float4*)(q + W_OUT)         = lo;  *(float4*)(q + W_OUT + 4)     = hi;
    hup(e1, lane, lo, hi);
    *(float4*)(q + 2 * W_OUT)     = lo;  *(float4*)(q + 2 * W_OUT + 4) = hi;
    hup(o1, lane, lo, hi);
    *(float4*)(q + 3 * W_OUT)     = lo;  *(float4*)(q + 3 * W_OUT + 4) = hi;
}

extern "C" void kernel_launch(void* const* d_in, const int* in_sizes, int n_in,
                              void* d_out, int out_size) {
    const float* x = (const float*)d_in[0];
    float* out = (float*)d_out;
    dim3 grid(H_IN / RPB, 128, 8);   // (row blocks, C, B)
    upsample2x_fir_kernel<<<grid, 256>>>(x, out);
}

// round 10
// speedup vs baseline: 1.7350x; 1.7350x over previous
#include <cuda_runtime.h>
#include <cstdint>

// 2x FIR upsample, depthwise separable [1,3,3,1]/4 per axis (factor=2 gain).
//   out[2i]   = 0.25*x[i-1] + 0.75*x[i]
//   out[2i+1] = 0.75*x[i]   + 0.25*x[i+1]
// Input (8,128,128,128) f32 -> Output (8,128,256,256) f32.
//
// Bulk-async I/O: one cp.async.bulk G->S for the 18-row input span (contiguous),
// compute in registers (vertical blend + shfl horizontal upsample), STS results
// to a 32-row output tile, one cp.async.bulk S->G (contiguous 32KB).

#define H_IN 128
#define W_IN 128
#define W_OUT 256
#define RPB 16                    // input rows per block
#define IN_TROWS (RPB + 2)        // staged rows r0-1 .. r0+16

__device__ __forceinline__ uint32_t s2u(const void* p) {
    return (uint32_t)__cvta_generic_to_shared(p);
}

__device__ __forceinline__ float4 blend(float wa, float4 a, float wb, float4 b) {
    return make_float4(wa*a.x + wb*b.x, wa*a.y + wb*b.y,
                       wa*a.z + wb*b.z, wa*a.w + wb*b.w);
}

// Horizontal 2x upsample: lane l holds cols 4l..4l+3; halo via shfl
// (zero at edges: W=128=32*4 spans the warp exactly).
__device__ __forceinline__ void hup(float4 v, int lane, float4& lo, float4& hi) {
    float left  = __shfl_up_sync(0xFFFFFFFFu, v.w, 1);
    float right = __shfl_down_sync(0xFFFFFFFFu, v.x, 1);
    if (lane == 0)  left  = 0.f;
    if (lane == 31) right = 0.f;
    lo.x = 0.25f * left + 0.75f * v.x;
    lo.y = 0.75f * v.x  + 0.25f * v.y;
    lo.z = 0.25f * v.x  + 0.75f * v.y;
    lo.w = 0.75f * v.y  + 0.25f * v.z;
    hi.x = 0.25f * v.y  + 0.75f * v.z;
    hi.y = 0.75f * v.z  + 0.25f * v.w;
    hi.z = 0.25f * v.z  + 0.75f * v.w;
    hi.w = 0.75f * v.w  + 0.25f * right;
}

__global__ __launch_bounds__(256)
void upsample2x_fir_kernel(const float* __restrict__ x, float* __restrict__ out) {
    __shared__ __align__(16) float s_in[IN_TROWS * W_IN];     // 9216 B
    __shared__ __align__(16) float s_out[2 * RPB * W_OUT];    // 32768 B
    __shared__ __align__(8)  unsigned long long mbar;

    const int tid  = threadIdx.x;
    const int rb   = blockIdx.x;                              // 0..7
    const int chan = blockIdx.z * gridDim.y + blockIdx.y;     // b*C + c
    const float* xp = x   + (size_t)chan * (H_IN * W_IN);
    float*       op = out + (size_t)chan * (2 * H_IN * W_OUT);

    const int r0 = rb * RPB;
    const int lo_row = (r0 - 1 < 0) ? 0 : r0 - 1;
    const int hi_row = (r0 + 17 > H_IN) ? H_IN : r0 + 17;     // exclusive
    const uint32_t nbytes = (uint32_t)(hi_row - lo_row) * (W_IN * 4);

    if (tid == 0) {
        asm volatile("mbarrier.init.shared::cta.b64 [%0], 1;"
                     :: "r"(s2u(&mbar)) : "memory");
    }
    __syncthreads();   // mbar init visible to all before any wait

    if (tid == 0) {
        asm volatile("mbarrier.arrive.expect_tx.shared::cta.b64 _, [%0], %1;"
                     :: "r"(s2u(&mbar)), "r"(nbytes) : "memory");
        const uint32_t dst = s2u(s_in) + (uint32_t)(lo_row - (r0 - 1)) * (W_IN * 4);
        asm volatile("cp.async.bulk.shared::cta.global.mbarrier::complete_tx::bytes "
                     "[%0], [%1], %2, [%3];"
                     :: "r"(dst), "l"(xp + (size_t)lo_row * W_IN),
                        "r"(nbytes), "r"(s2u(&mbar)) : "memory");
    }

    // Zero clipped halo rows (regions the bulk load does not touch).
    if (r0 == 0 && tid < 32)
        *(float4*)&s_in[tid * 4] = make_float4(0.f, 0.f, 0.f, 0.f);
    if (r0 + RPB == H_IN && tid < 32)
        *(float4*)&s_in[(IN_TROWS - 1) * W_IN + tid * 4] = make_float4(0.f, 0.f, 0.f, 0.f);

    // Wait for bulk load (parity 0).
    {
        const uint32_t mb = s2u(&mbar);
        uint32_t done;
        asm volatile(
            "{\n\t.reg .pred p;\n\t"
            "mbarrier.try_wait.parity.acquire.cta.shared::cta.b64 p, [%1], 0;\n\t"
            "selp.b32 %0, 1, 0, p;\n\t}"
            : "=r"(done) : "r"(mb) : "memory");
        if (!done) {
            asm volatile(
                "{\n\t.reg .pred P1;\n\t"
                "W_%=:\n\t"
                "mbarrier.try_wait.parity.acquire.cta.shared::cta.b64 P1, [%0], 0, 0x989680;\n\t"
                "@P1 bra.uni D_%=;\n\t"
                "bra.uni W_%=;\n\t"
                "D_%=:\n\t}"
                :: "r"(mb) : "memory");
        }
    }
    __syncthreads();   // also orders the zero-fill STS

    // ---- compute: thread (lane, ty) handles input rows r0+2ty, r0+2ty+1 ----
    const int lane = tid & 31;
    const int ty   = tid >> 5;            // 0..7
    const int jc   = lane * 4;            // col base

    // s_in row s holds input row r0-1+s.
    const float4 m0 = *(const float4*)&s_in[(2*ty    ) * W_IN + jc];
    const float4 m1 = *(const float4*)&s_in[(2*ty + 1) * W_IN + jc];
    const float4 m2 = *(const float4*)&s_in[(2*ty + 2) * W_IN + jc];
    const float4 m3 = *(const float4*)&s_in[(2*ty + 3) * W_IN + jc];

    const float4 e0 = blend(0.25f, m0, 0.75f, m1);   // out tile row 4ty
    const float4 o0 = blend(0.75f, m1, 0.25f, m2);   // 4ty+1
    const float4 e1 = blend(0.25f, m1, 0.75f, m2);   // 4ty+2
    const float4 o1 = blend(0.75f, m2, 0.25f, m3);   // 4ty+3

    float* q = &s_out[(4 * ty) * W_OUT + 2 * jc];

    float4 lov, hiv;
    hup(e0, lane, lov, hiv);
    *(float4*)(q)                 = lov;  *(float4*)(q + 4)             = hiv;
    hup(o0, lane, lov, hiv);
    *(float4*)(q + W_OUT)         = lov;  *(float4*)(q + W_OUT + 4)     = hiv;
    hup(e1, lane, lov, hiv);
    *(float4*)(q + 2 * W_OUT)     = lov;  *(float4*)(q + 2 * W_OUT + 4) = hiv;
    hup(o1, lane, lov, hiv);
    *(float4*)(q + 3 * W_OUT)     = lov;  *(float4*)(q + 3 * W_OUT + 4) = hiv;

    __syncthreads();

    // ---- bulk store: 32 contiguous output rows = 32 KB ----
    if (tid == 0) {
        asm volatile("fence.proxy.async.shared::cta;" ::: "memory");
        asm volatile("cp.async.bulk.global.shared::cta.bulk_group [%0], [%1], %2;"
                     :: "l"(op + (size_t)(2 * r0) * W_OUT), "r"(s2u(s_out)),
                        "r"((uint32_t)(2 * RPB * W_OUT * 4)) : "memory");
        asm volatile("cp.async.bulk.commit_group;" ::: "memory");
        asm volatile("cp.async.bulk.wait_group 0;" ::: "memory");
    }
}

extern "C" void kernel_launch(void* const* d_in, const int* in_sizes, int n_in,
                              void* d_out, int out_size) {
    const float* x = (const float*)d_in[0];
    float* out = (float*)d_out;
    dim3 grid(H_IN / RPB, 128, 8);   // (row blocks, C, B)
    upsample2x_fir_kernel<<<grid, 256>>>(x, out);
}